// round 14
// baseline (speedup 1.0000x reference)
#include <cuda_runtime.h>

#define B_    16
#define CIN_  256
#define COUT_ 3
#define WDIM_ 512
#define INS   128
#define OUTS  256
#define FW    13
#define TR    16                  // output rows per upsample tile
#define IR    14                  // input rows staged per tile (TR/2 + 6)
#define CSPL  4                   // channel splits in einsum
#define CPB   (CIN_ / CSPL)       // 64 channels per block
#define PLN   (INS * INS)         // 16384 px per plane
#define BCP   (B_ * COUT_)        // 48 planes

// scratch (allocation-free rule: __device__ globals)
__device__ float g_part[CSPL * BCP * PLN];             // unclamped partial sums

// ---- packed f32x2 helpers ---------------------------------------------------
__device__ __forceinline__ unsigned long long pack2(float lo, float hi) {
    unsigned long long r;
    asm("mov.b64 %0, {%1, %2};" : "=l"(r) : "f"(lo), "f"(hi));
    return r;
}
__device__ __forceinline__ void unpack2(unsigned long long v, float& lo, float& hi) {
    asm("mov.b64 {%0, %1}, %2;" : "=f"(lo), "=f"(hi) : "l"(v));
}
#define FFMA2(acc, a, b) \
    asm("fma.rn.f32x2 %0, %1, %2, %0;" : "+l"(acc) : "l"(a), "l"(b))

// ---------------------------------------------------------------------------
// K1: fused styles + split-C partial einsum.
// grid (8 px-tiles, 16 b, 4 csplit) = 512 blocks, 512 threads (2 blocks/SM).
__global__ void __launch_bounds__(512, 2) k_einsum(
        const float* __restrict__ x,
        const float* __restrict__ w,
        const float* __restrict__ aw,
        const float* __restrict__ abias,
        const float* __restrict__ cw) {
    const int b    = blockIdx.y;
    const int s    = blockIdx.z;
    const int tid  = threadIdx.x;
    const int lane = tid & 31;
    const int wid  = tid >> 5;   // 0..15

    __shared__ __align__(16) unsigned long long c2[COUT_ * CPB];

    // ---- phase A: styles for channels [s*64, s*64+64) ----
    {
        const float4* w4 = (const float4*)(w + (size_t)b * WDIM_);
        float4 wv0 = w4[lane];
        float4 wv1 = w4[32 + lane];
        float4 wv2 = w4[64 + lane];
        float4 wv3 = w4[96 + lane];
        #pragma unroll
        for (int c8 = 0; c8 < 4; c8++) {
            const int i  = s * CPB + wid * 4 + c8;   // global channel
            const float4* a4 = (const float4*)(aw + (size_t)i * WDIM_);
            float4 av0 = a4[lane];
            float4 av1 = a4[32 + lane];
            float4 av2 = a4[64 + lane];
            float4 av3 = a4[96 + lane];
            float sacc = av0.x * wv0.x + av0.y * wv0.y + av0.z * wv0.z + av0.w * wv0.w
                       + av1.x * wv1.x + av1.y * wv1.y + av1.z * wv1.z + av1.w * wv1.w
                       + av2.x * wv2.x + av2.y * wv2.y + av2.z * wv2.z + av2.w * wv2.w
                       + av3.x * wv3.x + av3.y * wv3.y + av3.z * wv3.z + av3.w * wv3.w;
            #pragma unroll
            for (int off = 16; off; off >>= 1)
                sacc += __shfl_xor_sync(0xffffffffu, sacc, off);
            if (lane == 0) {
                float style = (sacc * 0.04419417382415922f /*1/sqrt(512)*/
                               + abias[i]) * 0.0625f /*1/sqrt(256)*/;
                const int j = wid * 4 + c8;          // local channel 0..63
                #pragma unroll
                for (int o = 0; o < COUT_; o++) {
                    float v = cw[o * CIN_ + i] * style;
                    c2[o * CPB + j] = pack2(v, v);
                }
            }
        }
    }
    __syncthreads();

    // ---- phase B: streaming channel reduction ----
    const int base = blockIdx.x * 2048 + tid * 4;

    unsigned long long a00 = 0ull, a01 = 0ull;
    unsigned long long a10 = 0ull, a11 = 0ull;
    unsigned long long a20 = 0ull, a21 = 0ull;

    const float* xb = x + ((size_t)b * CIN_ + s * CPB) * PLN + base;
    #pragma unroll 8
    for (int j = 0; j < CPB; j++) {
        float4 v = __ldcs((const float4*)(xb + (size_t)j * PLN));
        unsigned long long vlo = pack2(v.x, v.y);
        unsigned long long vhi = pack2(v.z, v.w);
        unsigned long long c0 = c2[j];
        unsigned long long c1 = c2[CPB + j];
        unsigned long long ck = c2[2 * CPB + j];
        FFMA2(a00, c0, vlo); FFMA2(a01, c0, vhi);
        FFMA2(a10, c1, vlo); FFMA2(a11, c1, vhi);
        FFMA2(a20, ck, vlo); FFMA2(a21, ck, vhi);
    }

    unsigned long long alo[3] = {a00, a10, a20};
    unsigned long long ahi[3] = {a01, a11, a21};
    #pragma unroll
    for (int o = 0; o < COUT_; o++) {
        float4 r;
        unpack2(alo[o], r.x, r.y);
        unpack2(ahi[o], r.z, r.w);
        *(float4*)(g_part + ((size_t)(s * BCP + b * COUT_ + o)) * PLN + base) = r;
    }
}

// ---------------------------------------------------------------------------
// K2: combine partials + bias + clamp, then fused separable polyphase x2
// upsample. grid (48 planes, 16 row-tiles of 16), 512 threads in two halves:
// half h does H-rows [h*7, h*7+7) and V output rows [h*8, h*8+8).
__global__ void __launch_bounds__(512) k_upfused(
        float* __restrict__ out,
        const float* __restrict__ cbias,
        const float* __restrict__ filt) {
    const int plane = blockIdx.x;          // b*3 + o
    const int tile  = blockIdx.y;
    const int r0    = tile * TR;           // first output row (even)
    const int s0    = r0 >> 1;             // first "center" input row
    const int tid   = threadIdx.x;
    const int col   = tid & 255;
    const int half  = tid >> 8;            // 0 or 1
    const float bia = cbias[plane % COUT_];

    __shared__ __align__(16) float in_s[IR][INS];
    __shared__ __align__(16) float h_s[IR][OUTS];
    __shared__ __align__(16) float kf[16];           // padded to 16 floats

    if (tid < FW) kf[tid] = 2.0f * filt[FW - 1 - tid];

    // stage rows s0-3 .. s0+10: float4 combine of 4 partials + bias + clamp
    const float* pp = g_part + (size_t)plane * PLN;
    {
        int idx = tid;                     // 448 items, 512 threads: <=1 each
        if (idx < IR * (INS / 4)) {
            int r  = idx >> 5;             // /32 float4 per row
            int c4 = idx & 31;
            int gr = s0 - 3 + r;
            float4 v = make_float4(0.f, 0.f, 0.f, 0.f);
            if (gr >= 0 && gr < INS) {
                size_t off = (size_t)gr * INS + c4 * 4;
                float4 p0 = *(const float4*)(pp + off);
                float4 p1 = *(const float4*)(pp + 1 * (size_t)BCP * PLN + off);
                float4 p2 = *(const float4*)(pp + 2 * (size_t)BCP * PLN + off);
                float4 p3 = *(const float4*)(pp + 3 * (size_t)BCP * PLN + off);
                v.x = fminf(fmaxf(p0.x + p1.x + p2.x + p3.x + bia, -256.f), 256.f);
                v.y = fminf(fmaxf(p0.y + p1.y + p2.y + p3.y + bia, -256.f), 256.f);
                v.z = fminf(fmaxf(p0.z + p1.z + p2.z + p3.z + bia, -256.f), 256.f);
                v.w = fminf(fmaxf(p0.w + p1.w + p2.w + p3.w + bia, -256.f), 256.f);
            }
            *(float4*)&in_s[r][c4 * 4] = v;
        }
    }
    __syncthreads();

    // ---- horizontal: output col n = col; half 0 rows 0..6, half 1 rows 7..13
    {
        const int n   = col;
        const int par = n & 1;
        const int cb  = (n >> 1) - 3;
        float wt[7];
        int   cc[7];
        #pragma unroll
        for (int j = 0; j < 7; j++) {
            int c   = cb + j;
            float v = par ? kf[2 * j] : ((j < 6) ? kf[2 * j + 1] : 0.f);
            bool ok = (c >= 0 && c < INS);
            cc[j] = ok ? c : 0;
            wt[j] = ok ? v : 0.f;
        }
        const int rbase = half * 7;
        #pragma unroll
        for (int r = 0; r < 7; r++) {
            float acc = 0.f;
            #pragma unroll
            for (int j = 0; j < 7; j++)
                acc += wt[j] * in_s[rbase + r][cc[j]];
            h_s[rbase + r][n] = acc;
        }
    }
    __syncthreads();

    // ---- vertical: half h covers output rows [h*8, h*8+8),
    // needing h_s rows [h*4, h*4+10) -> 10-register column cache.
    float hv[10];
    const int vb = half * 4;
    #pragma unroll
    for (int r = 0; r < 10; r++) hv[r] = h_s[vb + r][col];

    float* op = out + ((size_t)plane * OUTS + r0 + half * 8) * OUTS + col;
    #pragma unroll
    for (int k = 0; k < 8; k++) {
        const int lrb = k >> 1;            // local base row within hv
        float acc = 0.f;
        if (k & 1) {
            #pragma unroll
            for (int j = 0; j < 7; j++)
                acc += kf[2 * j] * hv[lrb + j];
        } else {
            #pragma unroll
            for (int j = 0; j < 6; j++)
                acc += kf[2 * j + 1] * hv[lrb + j];
        }
        op[k * OUTS] = acc;
    }
}

// ---------------------------------------------------------------------------
extern "C" void kernel_launch(void* const* d_in, const int* in_sizes, int n_in,
                              void* d_out, int out_size) {
    const float* x     = (const float*)d_in[0];  // [16,256,128,128]
    const float* w     = (const float*)d_in[1];  // [16,512]
    const float* aw    = (const float*)d_in[2];  // [256,512]
    const float* ab    = (const float*)d_in[3];  // [256]
    const float* cw    = (const float*)d_in[4];  // [3,256,1,1]
    const float* cb    = (const float*)d_in[5];  // [3]
    const float* filt  = (const float*)d_in[6];  // [13]
    float* out = (float*)d_out;                  // [16,3,256,256]

    k_einsum<<<dim3(8, B_, CSPL), 512>>>(x, w, aw, ab, cw);
    k_upfused<<<dim3(BCP, OUTS / TR), 512>>>(out, cb, filt);
}

// round 16
// speedup vs baseline: 1.0359x; 1.0359x over previous
#include <cuda_runtime.h>

#define B_    16
#define CIN_  256
#define COUT_ 3
#define WDIM_ 512
#define INS   128
#define OUTS  256
#define FW    13
#define TR    32                  // output rows per upsample tile
#define IRV   22                  // input rows staged per tile (TR/2 + 6)
#define INP   136                 // padded cols: src col -4 .. 131
#define CSPL  4                   // channel splits in einsum
#define CPB   (CIN_ / CSPL)       // 64 channels per block
#define PLN   (INS * INS)         // 16384 px per plane
#define BCP   (B_ * COUT_)        // 48 planes

// scratch (allocation-free rule: __device__ globals)
__device__ float g_part[CSPL * BCP * PLN];             // unclamped partial sums

// ---- packed f32x2 helpers ---------------------------------------------------
__device__ __forceinline__ unsigned long long pack2(float lo, float hi) {
    unsigned long long r;
    asm("mov.b64 %0, {%1, %2};" : "=l"(r) : "f"(lo), "f"(hi));
    return r;
}
__device__ __forceinline__ void unpack2(unsigned long long v, float& lo, float& hi) {
    asm("mov.b64 {%0, %1}, %2;" : "=f"(lo), "=f"(hi) : "l"(v));
}
#define FFMA2(acc, a, b) \
    asm("fma.rn.f32x2 %0, %1, %2, %0;" : "+l"(acc) : "l"(a), "l"(b))

// ---------------------------------------------------------------------------
// K1: fused styles + split-C partial einsum (unchanged from R13 — at DRAM floor).
// grid (8 px-tiles, 16 b, 4 csplit) = 512 blocks, 512 threads (2 blocks/SM).
__global__ void __launch_bounds__(512, 2) k_einsum(
        const float* __restrict__ x,
        const float* __restrict__ w,
        const float* __restrict__ aw,
        const float* __restrict__ abias,
        const float* __restrict__ cw) {
    const int b    = blockIdx.y;
    const int s    = blockIdx.z;
    const int tid  = threadIdx.x;
    const int lane = tid & 31;
    const int wid  = tid >> 5;   // 0..15

    __shared__ __align__(16) unsigned long long c2[COUT_ * CPB];

    // ---- phase A: styles for channels [s*64, s*64+64) ----
    {
        const float4* w4 = (const float4*)(w + (size_t)b * WDIM_);
        float4 wv0 = w4[lane];
        float4 wv1 = w4[32 + lane];
        float4 wv2 = w4[64 + lane];
        float4 wv3 = w4[96 + lane];
        #pragma unroll
        for (int c8 = 0; c8 < 4; c8++) {
            const int i  = s * CPB + wid * 4 + c8;   // global channel
            const float4* a4 = (const float4*)(aw + (size_t)i * WDIM_);
            float4 av0 = a4[lane];
            float4 av1 = a4[32 + lane];
            float4 av2 = a4[64 + lane];
            float4 av3 = a4[96 + lane];
            float sacc = av0.x * wv0.x + av0.y * wv0.y + av0.z * wv0.z + av0.w * wv0.w
                       + av1.x * wv1.x + av1.y * wv1.y + av1.z * wv1.z + av1.w * wv1.w
                       + av2.x * wv2.x + av2.y * wv2.y + av2.z * wv2.z + av2.w * wv2.w
                       + av3.x * wv3.x + av3.y * wv3.y + av3.z * wv3.z + av3.w * wv3.w;
            #pragma unroll
            for (int off = 16; off; off >>= 1)
                sacc += __shfl_xor_sync(0xffffffffu, sacc, off);
            if (lane == 0) {
                float style = (sacc * 0.04419417382415922f /*1/sqrt(512)*/
                               + abias[i]) * 0.0625f /*1/sqrt(256)*/;
                const int j = wid * 4 + c8;          // local channel 0..63
                #pragma unroll
                for (int o = 0; o < COUT_; o++) {
                    float v = cw[o * CIN_ + i] * style;
                    c2[o * CPB + j] = pack2(v, v);
                }
            }
        }
    }
    __syncthreads();

    // ---- phase B: streaming channel reduction ----
    const int base = blockIdx.x * 2048 + tid * 4;

    unsigned long long a00 = 0ull, a01 = 0ull;
    unsigned long long a10 = 0ull, a11 = 0ull;
    unsigned long long a20 = 0ull, a21 = 0ull;

    const float* xb = x + ((size_t)b * CIN_ + s * CPB) * PLN + base;
    #pragma unroll 8
    for (int j = 0; j < CPB; j++) {
        float4 v = __ldcs((const float4*)(xb + (size_t)j * PLN));
        unsigned long long vlo = pack2(v.x, v.y);
        unsigned long long vhi = pack2(v.z, v.w);
        unsigned long long c0 = c2[j];
        unsigned long long c1 = c2[CPB + j];
        unsigned long long ck = c2[2 * CPB + j];
        FFMA2(a00, c0, vlo); FFMA2(a01, c0, vhi);
        FFMA2(a10, c1, vlo); FFMA2(a11, c1, vhi);
        FFMA2(a20, ck, vlo); FFMA2(a21, ck, vhi);
    }

    unsigned long long alo[3] = {a00, a10, a20};
    unsigned long long ahi[3] = {a01, a11, a21};
    #pragma unroll
    for (int o = 0; o < COUT_; o++) {
        float4 r;
        unpack2(alo[o], r.x, r.y);
        unpack2(ahi[o], r.z, r.w);
        *(float4*)(g_part + ((size_t)(s * BCP + b * COUT_ + o)) * PLN + base) = r;
    }
}

// ---------------------------------------------------------------------------
// K2: combine partials + bias + clamp, then fused separable polyphase x2
// upsample. grid (48 planes, 8 row-tiles of 32), 512 threads.
// H stage: one thread per (row-group, source col m) produces BOTH output cols
// 2m and 2m+1 from one 7-sample window (padded smem, no predicates).
// V stage: two halves, 14-register column cache, filter taps in registers.
__global__ void __launch_bounds__(512) k_upfused(
        float* __restrict__ out,
        const float* __restrict__ cbias,
        const float* __restrict__ filt) {
    const int plane = blockIdx.x;          // b*3 + o
    const int tile  = blockIdx.y;
    const int r0    = tile * TR;           // first output row (even)
    const int s0    = r0 >> 1;             // first "center" input row
    const int tid   = threadIdx.x;
    const float bia = cbias[plane % COUT_];

    __shared__ __align__(16) float in_s[IRV][INP];   // src cols -4..131 (padded)
    __shared__ __align__(16) float h_s[IRV][OUTS];
    __shared__ __align__(16) float kf_s[16];

    if (tid < FW) kf_s[tid] = 2.0f * filt[FW - 1 - tid];

    // ---- stage rows s0-3 .. s0+18 with column padding; combine 4 partials ----
    const float* pp = g_part + (size_t)plane * PLN;
    for (int idx = tid; idx < IRV * (INP / 4); idx += 512) {
        int r  = idx / (INP / 4);          // 0..21
        int c4 = idx - r * (INP / 4);      // 0..33 ; src col = -4 + c4*4
        int gr = s0 - 3 + r;
        float4 v = make_float4(0.f, 0.f, 0.f, 0.f);
        if (gr >= 0 && gr < INS && c4 >= 1 && c4 <= 32) {
            size_t off = (size_t)gr * INS + (c4 - 1) * 4;
            float4 p0 = *(const float4*)(pp + off);
            float4 p1 = *(const float4*)(pp + 1 * (size_t)BCP * PLN + off);
            float4 p2 = *(const float4*)(pp + 2 * (size_t)BCP * PLN + off);
            float4 p3 = *(const float4*)(pp + 3 * (size_t)BCP * PLN + off);
            v.x = fminf(fmaxf(p0.x + p1.x + p2.x + p3.x + bia, -256.f), 256.f);
            v.y = fminf(fmaxf(p0.y + p1.y + p2.y + p3.y + bia, -256.f), 256.f);
            v.z = fminf(fmaxf(p0.z + p1.z + p2.z + p3.z + bia, -256.f), 256.f);
            v.w = fminf(fmaxf(p0.w + p1.w + p2.w + p3.w + bia, -256.f), 256.f);
        }
        *(float4*)&in_s[r][c4 * 4] = v;
    }
    __syncthreads();

    // filter taps in registers (broadcast reads, once)
    float kfe[6], kfo[7];
    #pragma unroll
    for (int j = 0; j < 6; j++) kfe[j] = kf_s[2 * j + 1];
    #pragma unroll
    for (int j = 0; j < 7; j++) kfo[j] = kf_s[2 * j];

    // ---- horizontal: thread (rg, m): rows rg, rg+4, ...; src col m ----
    {
        const int rg = tid >> 7;           // 0..3
        const int m  = tid & 127;          // source col
        for (int r = rg; r < IRV; r += 4) {
            const float* row = &in_s[r][m + 1];   // src col m-3 at padded idx m+1
            float v0 = row[0], v1 = row[1], v2 = row[2], v3 = row[3];
            float v4 = row[4], v5 = row[5], v6 = row[6];
            float ev = kfe[0] * v0 + kfe[1] * v1 + kfe[2] * v2
                     + kfe[3] * v3 + kfe[4] * v4 + kfe[5] * v5;
            float od = kfo[0] * v0 + kfo[1] * v1 + kfo[2] * v2
                     + kfo[3] * v3 + kfo[4] * v4 + kfo[5] * v5 + kfo[6] * v6;
            *(float2*)&h_s[r][2 * m] = make_float2(ev, od);
        }
    }
    __syncthreads();

    // ---- vertical: half h covers output rows [h*16, h*16+16),
    // needing h_s rows [h*8, h*8+14) -> 14-register column cache.
    const int col  = tid & 255;
    const int half = tid >> 8;             // 0 or 1
    float hv[14];
    const int vb = half * 8;
    #pragma unroll
    for (int r = 0; r < 14; r++) hv[r] = h_s[vb + r][col];

    float* op = out + ((size_t)plane * OUTS + r0 + half * 16) * OUTS + col;
    #pragma unroll
    for (int k = 0; k < 16; k++) {
        const int lrb = k >> 1;            // local base row within hv
        float acc = 0.f;
        if (k & 1) {
            #pragma unroll
            for (int j = 0; j < 7; j++)
                acc += kfo[j] * hv[lrb + j];
        } else {
            #pragma unroll
            for (int j = 0; j < 6; j++)
                acc += kfe[j] * hv[lrb + j];
        }
        op[k * OUTS] = acc;
    }
}

// ---------------------------------------------------------------------------
extern "C" void kernel_launch(void* const* d_in, const int* in_sizes, int n_in,
                              void* d_out, int out_size) {
    const float* x     = (const float*)d_in[0];  // [16,256,128,128]
    const float* w     = (const float*)d_in[1];  // [16,512]
    const float* aw    = (const float*)d_in[2];  // [256,512]
    const float* ab    = (const float*)d_in[3];  // [256]
    const float* cw    = (const float*)d_in[4];  // [3,256,1,1]
    const float* cb    = (const float*)d_in[5];  // [3]
    const float* filt  = (const float*)d_in[6];  // [13]
    float* out = (float*)d_out;                  // [16,3,256,256]

    k_einsum<<<dim3(8, B_, CSPL), 512>>>(x, w, aw, ab, cw);
    k_upfused<<<dim3(BCP, OUTS / TR), 512>>>(out, cb, filt);
}